// round 12
// baseline (speedup 1.0000x reference)
#include <cuda_runtime.h>
#include <cuda_bf16.h>
#include <math.h>

#define N_VIEWS   512
#define N_MULTI   32
#define MAX_SIFT  2048
#define N_MATCHES 1000000

#define FEAT_ELEMS (N_VIEWS * MAX_SIFT * 3)   // 3,145,728
#define FLAT_ROWS  (N_VIEWS * MAX_SIFT)       // 1,048,576
#define FEAT_GRID  (N_VIEWS * 2)              // 1024 blocks (2 per view)

// Per-view cumulative rotation (row-major 3x3) and translation.
__device__ float g_c33[N_VIEWS * 9];
__device__ float g_c3[N_VIEWS * 3];
// Padded 16B-per-point mirror of feat for the delta gather (1 sector/point).
__device__ float4 g_feat4[FLAT_ROWS];
// Scan-ready flag + completion counter (reset by last feat block each replay).
__device__ volatile int g_flag;
__device__ unsigned int g_done;

__device__ __forceinline__ void mat33_mul(const float* __restrict__ A,
                                          const float* __restrict__ B,
                                          float* __restrict__ C)
{
    // C = A @ B, row-major
    #pragma unroll
    for (int r = 0; r < 3; r++)
        #pragma unroll
        for (int c = 0; c < 3; c++)
            C[r * 3 + c] = fmaf(A[r * 3 + 0], B[0 * 3 + c],
                           fmaf(A[r * 3 + 1], B[1 * 3 + c],
                                A[r * 3 + 2] * B[2 * 3 + c]));
}

__device__ __forceinline__ void build_rot(const float* __restrict__ euler,
                                          int view, float* __restrict__ R)
{
    float a = euler[view * 3 + 0];
    float b = euler[view * 3 + 1];
    float c = euler[view * 3 + 2];
    float sa, ca, sb, cb, sc, cc;
    sincosf(a, &sa, &ca);
    sincosf(b, &sb, &cb);
    sincosf(c, &sc, &cc);
    R[0] = ca * cc + sa * sb * sc;
    R[1] = -sa * cb;
    R[2] = -ca * sc + sa * sb * cc;
    R[3] = sa * cc - ca * sb * sc;
    R[4] = ca * cb;
    R[5] = -sa * sc - ca * sb * cc;
    R[6] = cb * sc;
    R[7] = sb;
    R[8] = cb * cc;
}

// Block-0 scan: 128 threads x 4 views each. Computes g_c33[v] = rot0@..@rotv
// and g_c3[v] = cumsum(c_3)[v] for all 512 views.
__device__ void do_scan_block0(const float* __restrict__ euler,
                               const float* __restrict__ c_3)
{
    const int tid  = threadIdx.x;      // 0..127
    const int lane = tid & 31;
    const int warp = tid >> 5;         // 0..3

    // Pass 1: segment totals over views [4*tid, 4*tid+3]
    float M[9] = {1.f, 0.f, 0.f, 0.f, 1.f, 0.f, 0.f, 0.f, 1.f};
    float T[3] = {0.f, 0.f, 0.f};
    #pragma unroll
    for (int k = 0; k < 4; k++) {
        const int view = tid * 4 + k;
        float R[9], C[9];
        build_rot(euler, view, R);
        mat33_mul(M, R, C);
        #pragma unroll
        for (int j = 0; j < 9; j++) M[j] = C[j];
        T[0] += c_3[view * 3 + 0];
        T[1] += c_3[view * 3 + 1];
        T[2] += c_3[view * 3 + 2];
    }

    // Intra-warp inclusive Kogge-Stone (earlier segment on the left)
    #pragma unroll
    for (int d = 1; d < 32; d <<= 1) {
        float A[9], t0, t1, t2;
        #pragma unroll
        for (int j = 0; j < 9; j++) A[j] = __shfl_up_sync(0xffffffffu, M[j], d);
        t0 = __shfl_up_sync(0xffffffffu, T[0], d);
        t1 = __shfl_up_sync(0xffffffffu, T[1], d);
        t2 = __shfl_up_sync(0xffffffffu, T[2], d);
        if (lane >= d) {
            float C[9];
            mat33_mul(A, M, C);
            #pragma unroll
            for (int j = 0; j < 9; j++) M[j] = C[j];
            T[0] += t0; T[1] += t1; T[2] += t2;
        }
    }

    // Scan the 4 warp aggregates (inclusive) in shared memory
    __shared__ float aggM[4][9];
    __shared__ float aggT[4][3];
    if (lane == 31) {
        #pragma unroll
        for (int j = 0; j < 9; j++) aggM[warp][j] = M[j];
        aggT[warp][0] = T[0]; aggT[warp][1] = T[1]; aggT[warp][2] = T[2];
    }
    __syncthreads();
    if (tid == 0) {
        #pragma unroll
        for (int w = 1; w < 4; w++) {
            float A[9], B[9], C[9];
            #pragma unroll
            for (int j = 0; j < 9; j++) { A[j] = aggM[w - 1][j]; B[j] = aggM[w][j]; }
            mat33_mul(A, B, C);
            #pragma unroll
            for (int j = 0; j < 9; j++) aggM[w][j] = C[j];
            aggT[w][0] += aggT[w - 1][0];
            aggT[w][1] += aggT[w - 1][1];
            aggT[w][2] += aggT[w - 1][2];
        }
    }
    __syncthreads();

    // Exclusive prefix for this thread's segment
    float Mex[9], Tex[3];
    {
        float Msh[9], t0, t1, t2;
        #pragma unroll
        for (int j = 0; j < 9; j++) Msh[j] = __shfl_up_sync(0xffffffffu, M[j], 1);
        t0 = __shfl_up_sync(0xffffffffu, T[0], 1);
        t1 = __shfl_up_sync(0xffffffffu, T[1], 1);
        t2 = __shfl_up_sync(0xffffffffu, T[2], 1);

        if (lane == 0) {
            if (warp == 0) {
                Mex[0] = 1.f; Mex[1] = 0.f; Mex[2] = 0.f;
                Mex[3] = 0.f; Mex[4] = 1.f; Mex[5] = 0.f;
                Mex[6] = 0.f; Mex[7] = 0.f; Mex[8] = 1.f;
                Tex[0] = Tex[1] = Tex[2] = 0.f;
            } else {
                #pragma unroll
                for (int j = 0; j < 9; j++) Mex[j] = aggM[warp - 1][j];
                Tex[0] = aggT[warp - 1][0];
                Tex[1] = aggT[warp - 1][1];
                Tex[2] = aggT[warp - 1][2];
            }
        } else {
            if (warp == 0) {
                #pragma unroll
                for (int j = 0; j < 9; j++) Mex[j] = Msh[j];
                Tex[0] = t0; Tex[1] = t1; Tex[2] = t2;
            } else {
                float P[9];
                #pragma unroll
                for (int j = 0; j < 9; j++) P[j] = aggM[warp - 1][j];
                mat33_mul(P, Msh, Mex);
                Tex[0] = t0 + aggT[warp - 1][0];
                Tex[1] = t1 + aggT[warp - 1][1];
                Tex[2] = t2 + aggT[warp - 1][2];
            }
        }
    }

    // Pass 2: rescan segment, emitting per-view prefixes
    float P[9] = {Mex[0], Mex[1], Mex[2], Mex[3], Mex[4], Mex[5], Mex[6], Mex[7], Mex[8]};
    float Tp[3] = {Tex[0], Tex[1], Tex[2]};
    #pragma unroll
    for (int k = 0; k < 4; k++) {
        const int view = tid * 4 + k;
        float R[9], C[9];
        build_rot(euler, view, R);
        mat33_mul(P, R, C);
        #pragma unroll
        for (int j = 0; j < 9; j++) P[j] = C[j];
        Tp[0] += c_3[view * 3 + 0];
        Tp[1] += c_3[view * 3 + 1];
        Tp[2] += c_3[view * 3 + 2];
        #pragma unroll
        for (int j = 0; j < 9; j++) g_c33[view * 9 + j] = P[j];
        g_c3[view * 3 + 0] = Tp[0];
        g_c3[view * 3 + 1] = Tp[1];
        g_c3[view * 3 + 2] = Tp[2];
    }
}

// ---------------------------------------------------------------------------
// Fused feat kernel — LATE scan wait, 2 quads per thread (6 independent load
// streams per m-iteration for MLP). Block 0 runs the scan before streaming;
// all blocks wait for the flag only at the epilogue.
// ---------------------------------------------------------------------------
__global__ void __launch_bounds__(128)
feat_kernel(const float* __restrict__ euler,     // (512,3)
            const float* __restrict__ c_3,       // (512,1,3)
            const float* __restrict__ beta,      // (512,1,1,32)
            const float* __restrict__ pdepth,    // (512,3,32,2048)
            const float* __restrict__ pdepth0,   // (512,3,1,2048)
            float* __restrict__ feat)            // (512,2048,3)
{
    const int bid   = blockIdx.x;
    const int v     = bid >> 1;
    const int chunk = bid & 1;
    const int tid   = threadIdx.x;
    const int q0    = chunk * 256 + tid;         // first quad
    const int q1    = q0 + 128;                  // second quad

    __shared__ float sb[N_MULTI];
    __shared__ float sR[9];
    __shared__ float sT[3];

    if (bid == 0) {
        // Scan first so the flag publishes ~2us into the kernel.
        do_scan_block0(euler, c_3);
        __syncthreads();                   // all scan writes done
        if (tid == 0) {
            __threadfence();               // publish g_c33/g_c3
            g_flag = 1;
        }
    }

    if (tid < N_MULTI) sb[tid] = beta[v * N_MULTI + tid];
    __syncthreads();

    // ---- Mainloop: stream pdepth, accumulate (scan-independent) ----
    const float4* p0 = (const float4*)(pdepth0 + (size_t)v * 3 * MAX_SIFT);
    float4 acc[2][3];
    #pragma unroll
    for (int ch = 0; ch < 3; ch++) {
        acc[0][ch] = __ldcs(&p0[(size_t)ch * (MAX_SIFT / 4) + q0]);
        acc[1][ch] = __ldcs(&p0[(size_t)ch * (MAX_SIFT / 4) + q1]);
    }

    const float4* pd = (const float4*)(pdepth + (size_t)v * 3 * N_MULTI * MAX_SIFT);
    #pragma unroll
    for (int m = 0; m < N_MULTI; m++) {
        float bm = sb[m];
        #pragma unroll
        for (int ch = 0; ch < 3; ch++) {
            const float4* row = &pd[((size_t)ch * N_MULTI + m) * (MAX_SIFT / 4)];
            float4 pa = __ldcs(row + q0);
            float4 pb = __ldcs(row + q1);
            acc[0][ch].x = fmaf(bm, pa.x, acc[0][ch].x);
            acc[0][ch].y = fmaf(bm, pa.y, acc[0][ch].y);
            acc[0][ch].z = fmaf(bm, pa.z, acc[0][ch].z);
            acc[0][ch].w = fmaf(bm, pa.w, acc[0][ch].w);
            acc[1][ch].x = fmaf(bm, pb.x, acc[1][ch].x);
            acc[1][ch].y = fmaf(bm, pb.y, acc[1][ch].y);
            acc[1][ch].z = fmaf(bm, pb.z, acc[1][ch].z);
            acc[1][ch].w = fmaf(bm, pb.w, acc[1][ch].w);
        }
    }

    // ---- Late scan wait: flag set long before most blocks get here ----
    if (tid == 0) {
        while (g_flag == 0) { __nanosleep(64); }
        __threadfence();                   // acquire: order g_c33/g_c3 reads
    }
    __syncthreads();

    if (tid < 9)  sR[tid] = g_c33[v * 9 + tid];
    if (tid >= 32 && tid < 35) sT[tid - 32] = g_c3[v * 3 + (tid - 32)];
    __syncthreads();

    const float R0 = sR[0], R1 = sR[1], R2 = sR[2];
    const float R3 = sR[3], R4 = sR[4], R5 = sR[5];
    const float R6 = sR[6], R7 = sR[7], R8 = sR[8];
    const float T0 = sT[0], T1 = sT[1], T2 = sT[2];

    // ---- Epilogue: rotate + translate + stores, per quad ----
    #pragma unroll
    for (int g = 0; g < 2; g++) {
        const int q = (g == 0) ? q0 : q1;
        float o[4][3];
        const float ax[4] = {acc[g][0].x, acc[g][0].y, acc[g][0].z, acc[g][0].w};
        const float ay[4] = {acc[g][1].x, acc[g][1].y, acc[g][1].z, acc[g][1].w};
        const float az[4] = {acc[g][2].x, acc[g][2].y, acc[g][2].z, acc[g][2].w};
        #pragma unroll
        for (int e = 0; e < 4; e++) {
            o[e][0] = fmaf(ax[e], R0, fmaf(ay[e], R3, fmaf(az[e], R6, T0)));
            o[e][1] = fmaf(ax[e], R1, fmaf(ay[e], R4, fmaf(az[e], R7, T1)));
            o[e][2] = fmaf(ax[e], R2, fmaf(ay[e], R5, fmaf(az[e], R8, T2)));
        }

        // Required output layout (evict-first: never re-read by these kernels)
        float4* out = (float4*)(feat + (size_t)v * MAX_SIFT * 3) + (size_t)q * 3;
        __stcs(&out[0], make_float4(o[0][0], o[0][1], o[0][2], o[1][0]));
        __stcs(&out[1], make_float4(o[1][1], o[1][2], o[2][0], o[2][1]));
        __stcs(&out[2], make_float4(o[2][2], o[3][0], o[3][1], o[3][2]));

        // Padded mirror for the gather (default caching: delta reads it next)
        float4* f4 = g_feat4 + (size_t)v * MAX_SIFT + (size_t)q * 4;
        f4[0] = make_float4(o[0][0], o[0][1], o[0][2], 0.f);
        f4[1] = make_float4(o[1][0], o[1][1], o[1][2], 0.f);
        f4[2] = make_float4(o[2][0], o[2][1], o[2][2], 0.f);
        f4[3] = make_float4(o[3][0], o[3][1], o[3][2], 0.f);
    }

    // Replay-state reset: last block to finish clears flag + counter.
    __syncthreads();
    if (tid == 0) {
        unsigned int done = atomicAdd(&g_done, 1u);
        if (done == FEAT_GRID - 1) {
            g_flag = 0;
            g_done = 0u;
        }
    }
}

// ---------------------------------------------------------------------------
// delta via aligned float4 gathers, 2 matches per thread. At the diverged-
// gather wavefront floor — leave alone.
// matches is int32 (JAX x64-disabled downcast). g_feat4 is L2-resident.
// ---------------------------------------------------------------------------
__global__ void __launch_bounds__(256)
delta_kernel(const int* __restrict__ matches,   // (1e6, 2) int32
             float* __restrict__ delta)
{
    const int t    = blockIdx.x * blockDim.x + threadIdx.x;
    const int base = t * 2;
    if (base >= N_MATCHES) return;              // N_MATCHES % 2 == 0

    // one int4 = 2 (i0, i1) match pairs
    int4 mp = __ldg(&((const int4*)matches)[t]);

    unsigned ia0 = (unsigned)mp.x % FLAT_ROWS;
    unsigned ib0 = (unsigned)mp.y % FLAT_ROWS;
    unsigned ia1 = (unsigned)mp.z % FLAT_ROWS;
    unsigned ib1 = (unsigned)mp.w % FLAT_ROWS;

    float4 A0 = __ldg(&g_feat4[ia0]);
    float4 B0 = __ldg(&g_feat4[ib0]);
    float4 A1 = __ldg(&g_feat4[ia1]);
    float4 B1 = __ldg(&g_feat4[ib1]);

    float dx0 = A0.x - B0.x, dy0 = A0.y - B0.y, dz0 = A0.z - B0.z;
    float dx1 = A1.x - B1.x, dy1 = A1.y - B1.y, dz1 = A1.z - B1.z;

    float2 out;
    out.x = sqrtf(fmaf(dx0, dx0, fmaf(dy0, dy0, dz0 * dz0)));
    out.y = sqrtf(fmaf(dx1, dx1, fmaf(dy1, dy1, dz1 * dz1)));

    *(float2*)(delta + base) = out;
}

// ---------------------------------------------------------------------------
extern "C" void kernel_launch(void* const* d_in, const int* in_sizes, int n_in,
                              void* d_out, int out_size)
{
    const float* euler   = (const float*)d_in[0];   // c33_euler (512,3)
    const float* c_3     = (const float*)d_in[1];   // (512,1,3)
    const float* beta    = (const float*)d_in[2];   // (512,1,1,32)
    const float* pdepth  = (const float*)d_in[3];   // (512,3,32,2048)
    const float* pdepth0 = (const float*)d_in[4];   // (512,3,1,2048)
    const int*   matches = (const int*)d_in[5];     // (1e6,2) int32

    float* feat  = (float*)d_out;              // first 3,145,728 floats
    float* delta = feat + FEAT_ELEMS;          // next 1,000,000 floats

    feat_kernel<<<FEAT_GRID, 128>>>(euler, c_3, beta, pdepth, pdepth0, feat);

    const int dthreads = (N_MATCHES + 1) / 2;                // 500,000
    delta_kernel<<<(dthreads + 255) / 256, 256>>>(matches, delta);
}

// round 13
// speedup vs baseline: 1.0517x; 1.0517x over previous
#include <cuda_runtime.h>
#include <cuda_bf16.h>
#include <math.h>

#define N_VIEWS   512
#define N_MULTI   32
#define MAX_SIFT  2048
#define N_MATCHES 1000000

#define FEAT_ELEMS (N_VIEWS * MAX_SIFT * 3)   // 3,145,728
#define FLAT_ROWS  (N_VIEWS * MAX_SIFT)       // 1,048,576
#define FEAT_GRID  (N_VIEWS * 4)              // 2048 blocks (4 per view)

// Per-view cumulative rotation (row-major 3x3) and translation.
__device__ float g_c33[N_VIEWS * 9];
__device__ float g_c3[N_VIEWS * 3];
// Padded 16B-per-point mirror of feat for the delta gather (1 sector/point).
__device__ float4 g_feat4[FLAT_ROWS];
// Scan-ready flag + completion counter (reset by last feat block each replay).
__device__ volatile int g_flag;
__device__ unsigned int g_done;

__device__ __forceinline__ void mat33_mul(const float* __restrict__ A,
                                          const float* __restrict__ B,
                                          float* __restrict__ C)
{
    // C = A @ B, row-major
    #pragma unroll
    for (int r = 0; r < 3; r++)
        #pragma unroll
        for (int c = 0; c < 3; c++)
            C[r * 3 + c] = fmaf(A[r * 3 + 0], B[0 * 3 + c],
                           fmaf(A[r * 3 + 1], B[1 * 3 + c],
                                A[r * 3 + 2] * B[2 * 3 + c]));
}

__device__ __forceinline__ void build_rot(const float* __restrict__ euler,
                                          int view, float* __restrict__ R)
{
    float a = euler[view * 3 + 0];
    float b = euler[view * 3 + 1];
    float c = euler[view * 3 + 2];
    float sa, ca, sb, cb, sc, cc;
    sincosf(a, &sa, &ca);
    sincosf(b, &sb, &cb);
    sincosf(c, &sc, &cc);
    R[0] = ca * cc + sa * sb * sc;
    R[1] = -sa * cb;
    R[2] = -ca * sc + sa * sb * cc;
    R[3] = sa * cc - ca * sb * sc;
    R[4] = ca * cb;
    R[5] = -sa * sc - ca * sb * cc;
    R[6] = cb * sc;
    R[7] = sb;
    R[8] = cb * cc;
}

// Block-0 scan: 128 threads x 4 views each. Computes g_c33[v] = rot0@..@rotv
// and g_c3[v] = cumsum(c_3)[v] for all 512 views.
__device__ void do_scan_block0(const float* __restrict__ euler,
                               const float* __restrict__ c_3)
{
    const int tid  = threadIdx.x;      // 0..127
    const int lane = tid & 31;
    const int warp = tid >> 5;         // 0..3

    // Pass 1: segment totals over views [4*tid, 4*tid+3]
    float M[9] = {1.f, 0.f, 0.f, 0.f, 1.f, 0.f, 0.f, 0.f, 1.f};
    float T[3] = {0.f, 0.f, 0.f};
    #pragma unroll
    for (int k = 0; k < 4; k++) {
        const int view = tid * 4 + k;
        float R[9], C[9];
        build_rot(euler, view, R);
        mat33_mul(M, R, C);
        #pragma unroll
        for (int j = 0; j < 9; j++) M[j] = C[j];
        T[0] += c_3[view * 3 + 0];
        T[1] += c_3[view * 3 + 1];
        T[2] += c_3[view * 3 + 2];
    }

    // Intra-warp inclusive Kogge-Stone (earlier segment on the left)
    #pragma unroll
    for (int d = 1; d < 32; d <<= 1) {
        float A[9], t0, t1, t2;
        #pragma unroll
        for (int j = 0; j < 9; j++) A[j] = __shfl_up_sync(0xffffffffu, M[j], d);
        t0 = __shfl_up_sync(0xffffffffu, T[0], d);
        t1 = __shfl_up_sync(0xffffffffu, T[1], d);
        t2 = __shfl_up_sync(0xffffffffu, T[2], d);
        if (lane >= d) {
            float C[9];
            mat33_mul(A, M, C);
            #pragma unroll
            for (int j = 0; j < 9; j++) M[j] = C[j];
            T[0] += t0; T[1] += t1; T[2] += t2;
        }
    }

    // Scan the 4 warp aggregates (inclusive) in shared memory
    __shared__ float aggM[4][9];
    __shared__ float aggT[4][3];
    if (lane == 31) {
        #pragma unroll
        for (int j = 0; j < 9; j++) aggM[warp][j] = M[j];
        aggT[warp][0] = T[0]; aggT[warp][1] = T[1]; aggT[warp][2] = T[2];
    }
    __syncthreads();
    if (tid == 0) {
        #pragma unroll
        for (int w = 1; w < 4; w++) {
            float A[9], B[9], C[9];
            #pragma unroll
            for (int j = 0; j < 9; j++) { A[j] = aggM[w - 1][j]; B[j] = aggM[w][j]; }
            mat33_mul(A, B, C);
            #pragma unroll
            for (int j = 0; j < 9; j++) aggM[w][j] = C[j];
            aggT[w][0] += aggT[w - 1][0];
            aggT[w][1] += aggT[w - 1][1];
            aggT[w][2] += aggT[w - 1][2];
        }
    }
    __syncthreads();

    // Exclusive prefix for this thread's segment
    float Mex[9], Tex[3];
    {
        float Msh[9], t0, t1, t2;
        #pragma unroll
        for (int j = 0; j < 9; j++) Msh[j] = __shfl_up_sync(0xffffffffu, M[j], 1);
        t0 = __shfl_up_sync(0xffffffffu, T[0], 1);
        t1 = __shfl_up_sync(0xffffffffu, T[1], 1);
        t2 = __shfl_up_sync(0xffffffffu, T[2], 1);

        if (lane == 0) {
            if (warp == 0) {
                Mex[0] = 1.f; Mex[1] = 0.f; Mex[2] = 0.f;
                Mex[3] = 0.f; Mex[4] = 1.f; Mex[5] = 0.f;
                Mex[6] = 0.f; Mex[7] = 0.f; Mex[8] = 1.f;
                Tex[0] = Tex[1] = Tex[2] = 0.f;
            } else {
                #pragma unroll
                for (int j = 0; j < 9; j++) Mex[j] = aggM[warp - 1][j];
                Tex[0] = aggT[warp - 1][0];
                Tex[1] = aggT[warp - 1][1];
                Tex[2] = aggT[warp - 1][2];
            }
        } else {
            if (warp == 0) {
                #pragma unroll
                for (int j = 0; j < 9; j++) Mex[j] = Msh[j];
                Tex[0] = t0; Tex[1] = t1; Tex[2] = t2;
            } else {
                float P[9];
                #pragma unroll
                for (int j = 0; j < 9; j++) P[j] = aggM[warp - 1][j];
                mat33_mul(P, Msh, Mex);
                Tex[0] = t0 + aggT[warp - 1][0];
                Tex[1] = t1 + aggT[warp - 1][1];
                Tex[2] = t2 + aggT[warp - 1][2];
            }
        }
    }

    // Pass 2: rescan segment, emitting per-view prefixes
    float P[9] = {Mex[0], Mex[1], Mex[2], Mex[3], Mex[4], Mex[5], Mex[6], Mex[7], Mex[8]};
    float Tp[3] = {Tex[0], Tex[1], Tex[2]};
    #pragma unroll
    for (int k = 0; k < 4; k++) {
        const int view = tid * 4 + k;
        float R[9], C[9];
        build_rot(euler, view, R);
        mat33_mul(P, R, C);
        #pragma unroll
        for (int j = 0; j < 9; j++) P[j] = C[j];
        Tp[0] += c_3[view * 3 + 0];
        Tp[1] += c_3[view * 3 + 1];
        Tp[2] += c_3[view * 3 + 2];
        #pragma unroll
        for (int j = 0; j < 9; j++) g_c33[view * 9 + j] = P[j];
        g_c3[view * 3 + 0] = Tp[0];
        g_c3[view * 3 + 1] = Tp[1];
        g_c3[view * 3 + 2] = Tp[2];
    }
}

// ---------------------------------------------------------------------------
// Fused feat kernel — LATE scan wait, lean epilogue. Every block streams
// immediately (accumulation is scan-independent); block 0 runs the scan
// before streaming. At the epilogue all threads spin on the flag directly
// (usually already set) and read R/T via uniform broadcast __ldg — no smem
// staging, no extra __syncthreads.
// ---------------------------------------------------------------------------
__global__ void __launch_bounds__(128)
feat_kernel(const float* __restrict__ euler,     // (512,3)
            const float* __restrict__ c_3,       // (512,1,3)
            const float* __restrict__ beta,      // (512,1,1,32)
            const float* __restrict__ pdepth,    // (512,3,32,2048)
            const float* __restrict__ pdepth0,   // (512,3,1,2048)
            float* __restrict__ feat)            // (512,2048,3)
{
    const int bid   = blockIdx.x;
    const int v     = bid >> 2;
    const int chunk = bid & 3;
    const int tid   = threadIdx.x;
    const int q     = chunk * 128 + tid;   // quad index within view

    __shared__ float sb[N_MULTI];

    if (bid == 0) {
        // Scan first so the flag publishes ~2us into the kernel.
        do_scan_block0(euler, c_3);
        __syncthreads();                   // all scan writes done
        if (tid == 0) {
            __threadfence();               // publish g_c33/g_c3
            g_flag = 1;
        }
    }

    if (tid < N_MULTI) sb[tid] = beta[v * N_MULTI + tid];
    __syncthreads();

    // ---- Mainloop: stream pdepth, accumulate (scan-independent) ----
    const float4* p0 = (const float4*)(pdepth0 + (size_t)v * 3 * MAX_SIFT);
    float4 acc[3];
    #pragma unroll
    for (int ch = 0; ch < 3; ch++)
        acc[ch] = __ldcs(&p0[(size_t)ch * (MAX_SIFT / 4) + q]);

    const float4* pd = (const float4*)(pdepth + (size_t)v * 3 * N_MULTI * MAX_SIFT);
    #pragma unroll
    for (int m = 0; m < N_MULTI; m++) {
        float bm = sb[m];
        #pragma unroll
        for (int ch = 0; ch < 3; ch++) {
            float4 p = __ldcs(&pd[((size_t)ch * N_MULTI + m) * (MAX_SIFT / 4) + q]);
            acc[ch].x = fmaf(bm, p.x, acc[ch].x);
            acc[ch].y = fmaf(bm, p.y, acc[ch].y);
            acc[ch].z = fmaf(bm, p.z, acc[ch].z);
            acc[ch].w = fmaf(bm, p.w, acc[ch].w);
        }
    }

    // ---- Late scan wait: flag set ~60us before most blocks get here ----
    while (g_flag == 0) { __nanosleep(64); }
    __threadfence();                       // order g_c33/g_c3 reads

    // Uniform broadcast loads (all lanes same address -> 1 wavefront, L2-hot)
    const float R0 = __ldg(&g_c33[v * 9 + 0]);
    const float R1 = __ldg(&g_c33[v * 9 + 1]);
    const float R2 = __ldg(&g_c33[v * 9 + 2]);
    const float R3 = __ldg(&g_c33[v * 9 + 3]);
    const float R4 = __ldg(&g_c33[v * 9 + 4]);
    const float R5 = __ldg(&g_c33[v * 9 + 5]);
    const float R6 = __ldg(&g_c33[v * 9 + 6]);
    const float R7 = __ldg(&g_c33[v * 9 + 7]);
    const float R8 = __ldg(&g_c33[v * 9 + 8]);
    const float T0 = __ldg(&g_c3[v * 3 + 0]);
    const float T1 = __ldg(&g_c3[v * 3 + 1]);
    const float T2 = __ldg(&g_c3[v * 3 + 2]);

    // ---- Epilogue: rotate + translate ----
    float o[4][3];
    const float ax[4] = {acc[0].x, acc[0].y, acc[0].z, acc[0].w};
    const float ay[4] = {acc[1].x, acc[1].y, acc[1].z, acc[1].w};
    const float az[4] = {acc[2].x, acc[2].y, acc[2].z, acc[2].w};
    #pragma unroll
    for (int e = 0; e < 4; e++) {
        o[e][0] = fmaf(ax[e], R0, fmaf(ay[e], R3, fmaf(az[e], R6, T0)));
        o[e][1] = fmaf(ax[e], R1, fmaf(ay[e], R4, fmaf(az[e], R7, T1)));
        o[e][2] = fmaf(ax[e], R2, fmaf(ay[e], R5, fmaf(az[e], R8, T2)));
    }

    // Required output layout: 12 consecutive floats (48B, 16B-aligned)
    float4* out = (float4*)(feat + (size_t)v * MAX_SIFT * 3) + (size_t)q * 3;
    out[0] = make_float4(o[0][0], o[0][1], o[0][2], o[1][0]);
    out[1] = make_float4(o[1][1], o[1][2], o[2][0], o[2][1]);
    out[2] = make_float4(o[2][2], o[3][0], o[3][1], o[3][2]);

    // Padded mirror for the gather: one aligned float4 per point
    float4* f4 = g_feat4 + (size_t)v * MAX_SIFT + (size_t)q * 4;
    f4[0] = make_float4(o[0][0], o[0][1], o[0][2], 0.f);
    f4[1] = make_float4(o[1][0], o[1][1], o[1][2], 0.f);
    f4[2] = make_float4(o[2][0], o[2][1], o[2][2], 0.f);
    f4[3] = make_float4(o[3][0], o[3][1], o[3][2], 0.f);

    // Replay-state reset: last block to finish clears flag + counter.
    __syncthreads();
    if (tid == 0) {
        unsigned int done = atomicAdd(&g_done, 1u);
        if (done == FEAT_GRID - 1) {
            g_flag = 0;
            g_done = 0u;
        }
    }
}

// ---------------------------------------------------------------------------
// delta via aligned float4 gathers, 2 matches per thread. At the diverged-
// gather wavefront floor — leave alone.
// matches is int32 (JAX x64-disabled downcast). g_feat4 is L2-resident.
// ---------------------------------------------------------------------------
__global__ void __launch_bounds__(256)
delta_kernel(const int* __restrict__ matches,   // (1e6, 2) int32
             float* __restrict__ delta)
{
    const int t    = blockIdx.x * blockDim.x + threadIdx.x;
    const int base = t * 2;
    if (base >= N_MATCHES) return;              // N_MATCHES % 2 == 0

    // one int4 = 2 (i0, i1) match pairs
    int4 mp = __ldg(&((const int4*)matches)[t]);

    unsigned ia0 = (unsigned)mp.x % FLAT_ROWS;
    unsigned ib0 = (unsigned)mp.y % FLAT_ROWS;
    unsigned ia1 = (unsigned)mp.z % FLAT_ROWS;
    unsigned ib1 = (unsigned)mp.w % FLAT_ROWS;

    float4 A0 = __ldg(&g_feat4[ia0]);
    float4 B0 = __ldg(&g_feat4[ib0]);
    float4 A1 = __ldg(&g_feat4[ia1]);
    float4 B1 = __ldg(&g_feat4[ib1]);

    float dx0 = A0.x - B0.x, dy0 = A0.y - B0.y, dz0 = A0.z - B0.z;
    float dx1 = A1.x - B1.x, dy1 = A1.y - B1.y, dz1 = A1.z - B1.z;

    float2 out;
    out.x = sqrtf(fmaf(dx0, dx0, fmaf(dy0, dy0, dz0 * dz0)));
    out.y = sqrtf(fmaf(dx1, dx1, fmaf(dy1, dy1, dz1 * dz1)));

    *(float2*)(delta + base) = out;
}

// ---------------------------------------------------------------------------
extern "C" void kernel_launch(void* const* d_in, const int* in_sizes, int n_in,
                              void* d_out, int out_size)
{
    const float* euler   = (const float*)d_in[0];   // c33_euler (512,3)
    const float* c_3     = (const float*)d_in[1];   // (512,1,3)
    const float* beta    = (const float*)d_in[2];   // (512,1,1,32)
    const float* pdepth  = (const float*)d_in[3];   // (512,3,32,2048)
    const float* pdepth0 = (const float*)d_in[4];   // (512,3,1,2048)
    const int*   matches = (const int*)d_in[5];     // (1e6,2) int32

    float* feat  = (float*)d_out;              // first 3,145,728 floats
    float* delta = feat + FEAT_ELEMS;          // next 1,000,000 floats

    feat_kernel<<<FEAT_GRID, 128>>>(euler, c_3, beta, pdepth, pdepth0, feat);

    const int dthreads = (N_MATCHES + 1) / 2;                // 500,000
    delta_kernel<<<(dthreads + 255) / 256, 256>>>(matches, delta);
}

// round 16
// speedup vs baseline: 1.0692x; 1.0167x over previous
#include <cuda_runtime.h>
#include <cuda_bf16.h>
#include <math.h>

#define N_VIEWS   512
#define N_MULTI   32
#define MAX_SIFT  2048
#define N_MATCHES 1000000

#define FEAT_ELEMS (N_VIEWS * MAX_SIFT * 3)   // 3,145,728
#define FLAT_ROWS  (N_VIEWS * MAX_SIFT)       // 1,048,576
#define FEAT_GRID  (N_VIEWS * 4)              // 2048 streamer blocks
// total grid = FEAT_GRID + 1; block 0 is the dedicated scan block (bid 0 is
// ALWAYS in wave 1, so the flag is guaranteed to publish — no livelock).

// Per-view cumulative rotation (row-major 3x3) and translation.
// NOTE: written and read within the same launch -> must NOT be read via __ldg.
__device__ float g_c33[N_VIEWS * 9];
__device__ float g_c3[N_VIEWS * 3];
// Padded 16B-per-point mirror of feat for the delta gather (1 sector/point).
__device__ float4 g_feat4[FLAT_ROWS];
// Scan-ready flag + completion counter (reset by last streamer each replay).
__device__ int g_flag;
__device__ unsigned int g_done;

__device__ __forceinline__ void mat33_mul(const float* __restrict__ A,
                                          const float* __restrict__ B,
                                          float* __restrict__ C)
{
    // C = A @ B, row-major
    #pragma unroll
    for (int r = 0; r < 3; r++)
        #pragma unroll
        for (int c = 0; c < 3; c++)
            C[r * 3 + c] = fmaf(A[r * 3 + 0], B[0 * 3 + c],
                           fmaf(A[r * 3 + 1], B[1 * 3 + c],
                                A[r * 3 + 2] * B[2 * 3 + c]));
}

__device__ __forceinline__ void build_rot(const float* __restrict__ euler,
                                          int view, float* __restrict__ R)
{
    float a = euler[view * 3 + 0];
    float b = euler[view * 3 + 1];
    float c = euler[view * 3 + 2];
    float sa, ca, sb, cb, sc, cc;
    sincosf(a, &sa, &ca);
    sincosf(b, &sb, &cb);
    sincosf(c, &sc, &cc);
    R[0] = ca * cc + sa * sb * sc;
    R[1] = -sa * cb;
    R[2] = -ca * sc + sa * sb * cc;
    R[3] = sa * cc - ca * sb * sc;
    R[4] = ca * cb;
    R[5] = -sa * sc - ca * sb * cc;
    R[6] = cb * sc;
    R[7] = sb;
    R[8] = cb * cc;
}

// Scan: 128 threads x 4 views each. Computes g_c33[v] = rot0@..@rotv and
// g_c3[v] = cumsum(c_3)[v] for all 512 views.
__device__ void do_scan(const float* __restrict__ euler,
                        const float* __restrict__ c_3)
{
    const int tid  = threadIdx.x;      // 0..127
    const int lane = tid & 31;
    const int warp = tid >> 5;         // 0..3

    // Pass 1: segment totals over views [4*tid, 4*tid+3]
    float M[9] = {1.f, 0.f, 0.f, 0.f, 1.f, 0.f, 0.f, 0.f, 1.f};
    float T[3] = {0.f, 0.f, 0.f};
    #pragma unroll
    for (int k = 0; k < 4; k++) {
        const int view = tid * 4 + k;
        float R[9], C[9];
        build_rot(euler, view, R);
        mat33_mul(M, R, C);
        #pragma unroll
        for (int j = 0; j < 9; j++) M[j] = C[j];
        T[0] += c_3[view * 3 + 0];
        T[1] += c_3[view * 3 + 1];
        T[2] += c_3[view * 3 + 2];
    }

    // Intra-warp inclusive Kogge-Stone (earlier segment on the left)
    #pragma unroll
    for (int d = 1; d < 32; d <<= 1) {
        float A[9], t0, t1, t2;
        #pragma unroll
        for (int j = 0; j < 9; j++) A[j] = __shfl_up_sync(0xffffffffu, M[j], d);
        t0 = __shfl_up_sync(0xffffffffu, T[0], d);
        t1 = __shfl_up_sync(0xffffffffu, T[1], d);
        t2 = __shfl_up_sync(0xffffffffu, T[2], d);
        if (lane >= d) {
            float C[9];
            mat33_mul(A, M, C);
            #pragma unroll
            for (int j = 0; j < 9; j++) M[j] = C[j];
            T[0] += t0; T[1] += t1; T[2] += t2;
        }
    }

    // Scan the 4 warp aggregates (inclusive) in shared memory
    __shared__ float aggM[4][9];
    __shared__ float aggT[4][3];
    if (lane == 31) {
        #pragma unroll
        for (int j = 0; j < 9; j++) aggM[warp][j] = M[j];
        aggT[warp][0] = T[0]; aggT[warp][1] = T[1]; aggT[warp][2] = T[2];
    }
    __syncthreads();
    if (tid == 0) {
        #pragma unroll
        for (int w = 1; w < 4; w++) {
            float A[9], B[9], C[9];
            #pragma unroll
            for (int j = 0; j < 9; j++) { A[j] = aggM[w - 1][j]; B[j] = aggM[w][j]; }
            mat33_mul(A, B, C);
            #pragma unroll
            for (int j = 0; j < 9; j++) aggM[w][j] = C[j];
            aggT[w][0] += aggT[w - 1][0];
            aggT[w][1] += aggT[w - 1][1];
            aggT[w][2] += aggT[w - 1][2];
        }
    }
    __syncthreads();

    // Exclusive prefix for this thread's segment
    float Mex[9], Tex[3];
    {
        float Msh[9], t0, t1, t2;
        #pragma unroll
        for (int j = 0; j < 9; j++) Msh[j] = __shfl_up_sync(0xffffffffu, M[j], 1);
        t0 = __shfl_up_sync(0xffffffffu, T[0], 1);
        t1 = __shfl_up_sync(0xffffffffu, T[1], 1);
        t2 = __shfl_up_sync(0xffffffffu, T[2], 1);

        if (lane == 0) {
            if (warp == 0) {
                Mex[0] = 1.f; Mex[1] = 0.f; Mex[2] = 0.f;
                Mex[3] = 0.f; Mex[4] = 1.f; Mex[5] = 0.f;
                Mex[6] = 0.f; Mex[7] = 0.f; Mex[8] = 1.f;
                Tex[0] = Tex[1] = Tex[2] = 0.f;
            } else {
                #pragma unroll
                for (int j = 0; j < 9; j++) Mex[j] = aggM[warp - 1][j];
                Tex[0] = aggT[warp - 1][0];
                Tex[1] = aggT[warp - 1][1];
                Tex[2] = aggT[warp - 1][2];
            }
        } else {
            if (warp == 0) {
                #pragma unroll
                for (int j = 0; j < 9; j++) Mex[j] = Msh[j];
                Tex[0] = t0; Tex[1] = t1; Tex[2] = t2;
            } else {
                float P[9];
                #pragma unroll
                for (int j = 0; j < 9; j++) P[j] = aggM[warp - 1][j];
                mat33_mul(P, Msh, Mex);
                Tex[0] = t0 + aggT[warp - 1][0];
                Tex[1] = t1 + aggT[warp - 1][1];
                Tex[2] = t2 + aggT[warp - 1][2];
            }
        }
    }

    // Pass 2: rescan segment, emitting per-view prefixes
    float P[9] = {Mex[0], Mex[1], Mex[2], Mex[3], Mex[4], Mex[5], Mex[6], Mex[7], Mex[8]};
    float Tp[3] = {Tex[0], Tex[1], Tex[2]};
    #pragma unroll
    for (int k = 0; k < 4; k++) {
        const int view = tid * 4 + k;
        float R[9], C[9];
        build_rot(euler, view, R);
        mat33_mul(P, R, C);
        #pragma unroll
        for (int j = 0; j < 9; j++) P[j] = C[j];
        Tp[0] += c_3[view * 3 + 0];
        Tp[1] += c_3[view * 3 + 1];
        Tp[2] += c_3[view * 3 + 2];
        #pragma unroll
        for (int j = 0; j < 9; j++) g_c33[view * 9 + j] = P[j];
        g_c3[view * 3 + 0] = Tp[0];
        g_c3[view * 3 + 1] = Tp[1];
        g_c3[view * 3 + 2] = Tp[2];
    }
}

// ---------------------------------------------------------------------------
// Fused feat kernel — dedicated scan block at bid 0 (always wave-1 resident).
// Streamer blocks (bids 1..FEAT_GRID) start their mainloop immediately and
// spin on an acquire-load of the flag only at the epilogue, by which point
// the scan (~2.5us) finished long ago. R/T are then read with PLAIN coherent
// loads (never __ldg: the arrays are written in this same launch, and __ldg
// loads may legally be hoisted above the spin).
// ---------------------------------------------------------------------------
__global__ void __launch_bounds__(128)
feat_kernel(const float* __restrict__ euler,     // (512,3)
            const float* __restrict__ c_3,       // (512,1,3)
            const float* __restrict__ beta,      // (512,1,1,32)
            const float* __restrict__ pdepth,    // (512,3,32,2048)
            const float* __restrict__ pdepth0,   // (512,3,1,2048)
            float* __restrict__ feat)            // (512,2048,3)
{
    const int bid = blockIdx.x;
    const int tid = threadIdx.x;

    if (bid == 0) {
        // Dedicated scan block: scan, publish, exit.
        do_scan(euler, c_3);
        __syncthreads();                   // all scan writes done
        if (tid == 0) {
            __threadfence();               // release: publish g_c33/g_c3
            *(volatile int*)&g_flag = 1;
        }
        return;
    }

    const int sbid  = bid - 1;             // streamer index 0..FEAT_GRID-1
    const int v     = sbid >> 2;
    const int chunk = sbid & 3;
    const int q     = chunk * 128 + tid;   // quad index within view

    __shared__ float sb[N_MULTI];
    if (tid < N_MULTI) sb[tid] = beta[v * N_MULTI + tid];
    __syncthreads();

    // ---- Mainloop: stream pdepth, accumulate (scan-independent) ----
    const float4* p0 = (const float4*)(pdepth0 + (size_t)v * 3 * MAX_SIFT);
    float4 acc[3];
    #pragma unroll
    for (int ch = 0; ch < 3; ch++)
        acc[ch] = __ldcs(&p0[(size_t)ch * (MAX_SIFT / 4) + q]);

    const float4* pd = (const float4*)(pdepth + (size_t)v * 3 * N_MULTI * MAX_SIFT);
    #pragma unroll
    for (int m = 0; m < N_MULTI; m++) {
        float bm = sb[m];
        #pragma unroll
        for (int ch = 0; ch < 3; ch++) {
            float4 p = __ldcs(&pd[((size_t)ch * N_MULTI + m) * (MAX_SIFT / 4) + q]);
            acc[ch].x = fmaf(bm, p.x, acc[ch].x);
            acc[ch].y = fmaf(bm, p.y, acc[ch].y);
            acc[ch].z = fmaf(bm, p.z, acc[ch].z);
            acc[ch].w = fmaf(bm, p.w, acc[ch].w);
        }
    }

    // ---- Late scan wait: acquire-load spin (flag set ~60us earlier) ----
    {
        int f;
        do {
            asm volatile("ld.acquire.gpu.global.s32 %0, [%1];"
                         : "=r"(f) : "l"(&g_flag) : "memory");
            if (f) break;
            __nanosleep(64);
        } while (true);
    }

    // Plain coherent loads, ordered after the spin by the asm memory clobber.
    const float R0 = g_c33[v * 9 + 0];
    const float R1 = g_c33[v * 9 + 1];
    const float R2 = g_c33[v * 9 + 2];
    const float R3 = g_c33[v * 9 + 3];
    const float R4 = g_c33[v * 9 + 4];
    const float R5 = g_c33[v * 9 + 5];
    const float R6 = g_c33[v * 9 + 6];
    const float R7 = g_c33[v * 9 + 7];
    const float R8 = g_c33[v * 9 + 8];
    const float T0 = g_c3[v * 3 + 0];
    const float T1 = g_c3[v * 3 + 1];
    const float T2 = g_c3[v * 3 + 2];

    // ---- Epilogue: rotate + translate ----
    float o[4][3];
    const float ax[4] = {acc[0].x, acc[0].y, acc[0].z, acc[0].w};
    const float ay[4] = {acc[1].x, acc[1].y, acc[1].z, acc[1].w};
    const float az[4] = {acc[2].x, acc[2].y, acc[2].z, acc[2].w};
    #pragma unroll
    for (int e = 0; e < 4; e++) {
        o[e][0] = fmaf(ax[e], R0, fmaf(ay[e], R3, fmaf(az[e], R6, T0)));
        o[e][1] = fmaf(ax[e], R1, fmaf(ay[e], R4, fmaf(az[e], R7, T1)));
        o[e][2] = fmaf(ax[e], R2, fmaf(ay[e], R5, fmaf(az[e], R8, T2)));
    }

    // Required output layout: 12 consecutive floats (48B, 16B-aligned)
    float4* out = (float4*)(feat + (size_t)v * MAX_SIFT * 3) + (size_t)q * 3;
    out[0] = make_float4(o[0][0], o[0][1], o[0][2], o[1][0]);
    out[1] = make_float4(o[1][1], o[1][2], o[2][0], o[2][1]);
    out[2] = make_float4(o[2][2], o[3][0], o[3][1], o[3][2]);

    // Padded mirror for the gather: one aligned float4 per point
    float4* f4 = g_feat4 + (size_t)v * MAX_SIFT + (size_t)q * 4;
    f4[0] = make_float4(o[0][0], o[0][1], o[0][2], 0.f);
    f4[1] = make_float4(o[1][0], o[1][1], o[1][2], 0.f);
    f4[2] = make_float4(o[2][0], o[2][1], o[2][2], 0.f);
    f4[3] = make_float4(o[3][0], o[3][1], o[3][2], 0.f);

    // Replay-state reset: last streamer to finish clears flag + counter.
    __syncthreads();
    if (tid == 0) {
        unsigned int done = atomicAdd(&g_done, 1u);
        if (done == FEAT_GRID - 1) {
            g_flag = 0;
            g_done = 0u;
        }
    }
}

// ---------------------------------------------------------------------------
// delta via aligned float4 gathers, 2 matches per thread. At the diverged-
// gather wavefront floor — leave alone. __ldg here IS valid: g_feat4 is
// read-only for the duration of THIS kernel.
// matches is int32 (JAX x64-disabled downcast). g_feat4 is L2-resident.
// ---------------------------------------------------------------------------
__global__ void __launch_bounds__(256)
delta_kernel(const int* __restrict__ matches,   // (1e6, 2) int32
             float* __restrict__ delta)
{
    const int t    = blockIdx.x * blockDim.x + threadIdx.x;
    const int base = t * 2;
    if (base >= N_MATCHES) return;              // N_MATCHES % 2 == 0

    // one int4 = 2 (i0, i1) match pairs
    int4 mp = __ldg(&((const int4*)matches)[t]);

    unsigned ia0 = (unsigned)mp.x % FLAT_ROWS;
    unsigned ib0 = (unsigned)mp.y % FLAT_ROWS;
    unsigned ia1 = (unsigned)mp.z % FLAT_ROWS;
    unsigned ib1 = (unsigned)mp.w % FLAT_ROWS;

    float4 A0 = __ldg(&g_feat4[ia0]);
    float4 B0 = __ldg(&g_feat4[ib0]);
    float4 A1 = __ldg(&g_feat4[ia1]);
    float4 B1 = __ldg(&g_feat4[ib1]);

    float dx0 = A0.x - B0.x, dy0 = A0.y - B0.y, dz0 = A0.z - B0.z;
    float dx1 = A1.x - B1.x, dy1 = A1.y - B1.y, dz1 = A1.z - B1.z;

    float2 out;
    out.x = sqrtf(fmaf(dx0, dx0, fmaf(dy0, dy0, dz0 * dz0)));
    out.y = sqrtf(fmaf(dx1, dx1, fmaf(dy1, dy1, dz1 * dz1)));

    *(float2*)(delta + base) = out;
}

// ---------------------------------------------------------------------------
extern "C" void kernel_launch(void* const* d_in, const int* in_sizes, int n_in,
                              void* d_out, int out_size)
{
    const float* euler   = (const float*)d_in[0];   // c33_euler (512,3)
    const float* c_3     = (const float*)d_in[1];   // (512,1,3)
    const float* beta    = (const float*)d_in[2];   // (512,1,1,32)
    const float* pdepth  = (const float*)d_in[3];   // (512,3,32,2048)
    const float* pdepth0 = (const float*)d_in[4];   // (512,3,1,2048)
    const int*   matches = (const int*)d_in[5];     // (1e6,2) int32

    float* feat  = (float*)d_out;              // first 3,145,728 floats
    float* delta = feat + FEAT_ELEMS;          // next 1,000,000 floats

    feat_kernel<<<FEAT_GRID + 1, 128>>>(euler, c_3, beta, pdepth, pdepth0, feat);

    const int dthreads = (N_MATCHES + 1) / 2;                // 500,000
    delta_kernel<<<(dthreads + 255) / 256, 256>>>(matches, delta);
}